// round 8
// baseline (speedup 1.0000x reference)
#include <cuda_runtime.h>
#include <math.h>

#define BB 32
#define H0 256
#define W0 512
#define NT 128
#define FULLMASK 0xffffffffu

// pair-vectorized warp layout (62 output cols per warp):
// per side: L0 9*4*32=1152, L1 5*2*32=320, L2 3*1*32=96, L3 2*1*32=64 -> 1632
#define L1_BASE 1152
#define L2_BASE 1472
#define L3_BASE 1568
#define SIDE_WARPS 1632
#define TOTAL_WARPS (SIDE_WARPS * 2)
#define NBLOCKS (TOTAL_WARPS / 4)   // 816; all boundaries divisible by 4

typedef unsigned long long u64;
#define AS_U64(v) (*reinterpret_cast<u64*>(&(v)))
#define AS_F2(v)  (*reinterpret_cast<float2*>(&(v)))

__device__ __forceinline__ float2 f2(float x, float y) { return make_float2(x, y); }
__device__ __forceinline__ float2 add2(float2 a, float2 b) {
    u64 ra = AS_U64(a), rb = AS_U64(b), rc;
    asm("add.rn.f32x2 %0,%1,%2;" : "=l"(rc) : "l"(ra), "l"(rb));
    return AS_F2(rc);
}
__device__ __forceinline__ float2 mul2(float2 a, float2 b) {
    u64 ra = AS_U64(a), rb = AS_U64(b), rc;
    asm("mul.rn.f32x2 %0,%1,%2;" : "=l"(rc) : "l"(ra), "l"(rb));
    return AS_F2(rc);
}
__device__ __forceinline__ float2 fma2(float2 a, float2 b, float2 c) {
    u64 ra = AS_U64(a), rb = AS_U64(b), rc = AS_U64(c), rd;
    asm("fma.rn.f32x2 %0,%1,%2,%3;" : "=l"(rd) : "l"(ra), "l"(rb), "l"(rc));
    return AS_F2(rd);
}
__device__ __forceinline__ float2 sub2(float2 a, float2 b) {
    u64 rb = AS_U64(b) ^ 0x8000000080000000ULL;
    return add2(a, AS_F2(rb));
}
__device__ __forceinline__ float2 abs2(float2 a) {
    u64 ra = AS_U64(a) & 0x7FFFFFFF7FFFFFFFULL;
    return AS_F2(ra);
}

// ---------------- scratch ----------------
__device__ float g_lp1[BB*3*128*256];
__device__ float g_rp1[BB*3*128*256];
__device__ float g_lp2[BB*3*64*128];
__device__ float g_rp2[BB*3*64*128];
__device__ float g_lp3[BB*3*32*64];
__device__ float g_rp3[BB*3*32*64];

// per level i, 8 slots: 0 dssim_l, 1 dssim_r, 2 l1_l, 3 l1_r, 4 lr_l, 5 lr_r, 6 ds_l, 7 ds_r
__device__ double g_acc[32];

// ---------------- reduction helper (stride-2 slots) ----------------
template<int NV>
__device__ __forceinline__ void block_accumulate2(float (&v)[NV], double* accs) {
    #pragma unroll
    for (int k = 0; k < NV; k++)
        #pragma unroll
        for (int o = 16; o > 0; o >>= 1)
            v[k] += __shfl_down_sync(FULLMASK, v[k], o);
    __shared__ float sh[NV][4];
    int lane = threadIdx.x & 31, w = threadIdx.x >> 5;
    if (lane == 0) {
        #pragma unroll
        for (int k = 0; k < NV; k++) sh[k][w] = v[k];
    }
    __syncthreads();
    if (threadIdx.x == 0) {
        #pragma unroll
        for (int k = 0; k < NV; k++) {
            float s = sh[k][0] + sh[k][1] + sh[k][2] + sh[k][3];
            atomicAdd(accs + 2 * k, (double)s);
        }
    }
}

__global__ void zero_acc_kernel() {
    if (threadIdx.x < 32) g_acc[threadIdx.x] = 0.0;
}

// ---------------- paired bilinear align-corners resize ----------------
__global__ void resize2_kernel(const float* __restrict__ srcA, float* __restrict__ dstA,
                               const float* __restrict__ srcB, float* __restrict__ dstB,
                               int BC, int h, int w, int nh, int nw) {
    int idx = blockIdx.x * blockDim.x + threadIdx.x;
    int total = BC * nh * nw;
    int which = 0;
    if (idx >= total) { idx -= total; which = 1; if (idx >= total) return; }
    const float* src = which ? srcB : srcA;
    float* dst = which ? dstB : dstA;
    int x  = idx % nw;
    int t  = idx / nw;
    int y  = t % nh;
    int bc = t / nh;
    float fy = (float)y * (float)(h - 1) / (float)(nh - 1);
    float fx = (float)x * (float)(w - 1) / (float)(nw - 1);
    int y0 = (int)floorf(fy); int y1 = min(y0 + 1, h - 1);
    int x0 = (int)floorf(fx); int x1 = min(x0 + 1, w - 1);
    float wy = fy - (float)y0, wx = fx - (float)x0;
    const float* s = src + (size_t)bc * h * w;
    float top = s[(size_t)y0 * w + x0] * (1.f - wx) + s[(size_t)y0 * w + x1] * wx;
    float bot = s[(size_t)y1 * w + x0] * (1.f - wx) + s[(size_t)y1 * w + x1] * wx;
    dst[idx] = top * (1.f - wy) + bot * wy;
}

// ---------------- fused loss: pair-vectorized + f32x2 + pipeline ----------
struct LevelArgs {
    const float* lp[4];
    const float* rp[4];
    const float* disp[4];
};

struct Row {
    float2 d, wf;
    float2 o0, o1;
    float2 a[3];
    float2 e0[3], e1[3];
};

__global__ __launch_bounds__(NT) void fused_all_kernel(LevelArgs args) {
    int lane = threadIdx.x & 31;
    int g = blockIdx.x * (NT / 32) + (threadIdx.x >> 5);
    int side = (g >= SIDE_WARPS) ? 1 : 0;
    g -= side * SIDE_WARPS;

    int lvl, base, wpi, nx, W, H, CH;
    if (g < L1_BASE)      { lvl = 0; base = 0;       wpi = 36; nx = 9; W = 512; H = 256; CH = 64; }
    else if (g < L2_BASE) { lvl = 1; base = L1_BASE; wpi = 10; nx = 5; W = 256; H = 128; CH = 64; }
    else if (g < L3_BASE) { lvl = 2; base = L2_BASE; wpi = 3;  nx = 3; W = 128; H = 64;  CH = 64; }
    else                  { lvl = 3; base = L3_BASE; wpi = 2;  nx = 2; W = 64;  H = 32;  CH = 32; }

    int r   = g - base;
    int b   = r / wpi;
    int rr  = r - b * wpi;
    int xsl = rr % nx;
    int ych = rr / nx;
    int y0  = ych * CH;
    int col0 = xsl * 62 - 2 + 2 * lane;   // even -> aligned float2
    int col1 = col0 + 1;

    int plane = H * W;
    const float* Ximg = side ? args.rp[lvl] : args.lp[lvl];
    const float* Gimg = side ? args.lp[lvl] : args.rp[lvl];
    const float* dbase = args.disp[lvl] + (size_t)b * 2 * plane;
    const float* dmy  = dbase + (side ? plane : 0);
    const float* doth = dbase + (side ? 0 : plane);
    float sgn = side ? (float)(W - 1) : -(float)(W - 1);

    bool c0ok = (col0 >= 0) & (col0 < W);
    bool c1ok = (col1 >= 0) & (col1 < W);
    bool vecok = (col0 >= 0) & (col1 < W);

    // static per-column emission masks
    float2 mL = f2((lane >= 1 && c0ok) ? 1.f : 0.f,
                   (lane <= 30 && c1ok) ? 1.f : 0.f);
    float2 mD = f2((mL.x != 0.f && col0 >= 1 && col0 <= W - 2) ? 1.f : 0.f,
                   (mL.y != 0.f && col1 >= 1 && col1 <= W - 2) ? 1.f : 0.f);
    float2 mX = f2((mL.x != 0.f && col0 <= W - 2) ? 1.f : 0.f,
                   (mL.y != 0.f && col1 <= W - 2) ? 1.f : 0.f);

    int ys = max(y0 - 2, 0);
    int ye = min(y0 + CH, H - 1);

    const float* Xb[3];
    const float* Gb[3];
    #pragma unroll
    for (int c = 0; c < 3; c++) {
        Xb[c] = Ximg + ((size_t)b * 3 + c) * plane;
        Gb[c] = Gimg + ((size_t)b * 3 + c) * plane;
    }

    auto loadPair = [&](const float* p, int off) -> float2 {
        if (vecok) return *reinterpret_cast<const float2*>(p + off + col0);
        float lx = c0ok ? __ldg(p + off + col0) : 0.f;
        float ly = c1ok ? __ldg(p + off + col1) : 0.f;
        return f2(lx, ly);
    };

    auto issue = [&](int y, float2 d) -> Row {
        Row rv;
        rv.d = d;
        int off = y * W;
        float xw0 = (float)col0 + d.x * sgn;
        float xw1 = (float)col1 + d.y * sgn;
        float f0 = floorf(xw0); int i0 = (int)f0; float wf0 = xw0 - f0;
        float f1 = floorf(xw1); int i1 = (int)f1; float wf1 = xw1 - f1;
        bool v00 = (i0 >= 0) & (i0 < W);
        bool v01 = (i0 >= -1) & (i0 < W - 1);
        bool v10 = (i1 >= 0) & (i1 < W);
        bool v11 = (i1 >= -1) & (i1 < W - 1);
        rv.wf = f2(wf0, wf1);
        rv.o0 = f2(v00 ? __ldg(doth + off + i0) : 0.f, v10 ? __ldg(doth + off + i1) : 0.f);
        rv.o1 = f2(v01 ? __ldg(doth + off + i0 + 1) : 0.f, v11 ? __ldg(doth + off + i1 + 1) : 0.f);
        #pragma unroll
        for (int c = 0; c < 3; c++) {
            rv.a[c]  = loadPair(Xb[c], off);
            rv.e0[c] = f2(v00 ? __ldg(Gb[c] + off + i0) : 0.f, v10 ? __ldg(Gb[c] + off + i1) : 0.f);
            rv.e1[c] = f2(v01 ? __ldg(Gb[c] + off + i0 + 1) : 0.f, v11 ? __ldg(Gb[c] + off + i1 + 1) : 0.f);
        }
        return rv;
    };

    // ring of horizontal window sums (3-row vertical ring), 5 quantities x 3 ch
    float2 s1[3][5], s2[3][5];
    #pragma unroll
    for (int c = 0; c < 3; c++)
        #pragma unroll
        for (int k = 0; k < 5; k++) { s1[c][k] = f2(0.f, 0.f); s2[c][k] = f2(0.f, 0.f); }
    float2 pX[3] = {f2(0,0), f2(0,0), f2(0,0)};
    float2 pd = f2(0, 0);

    float vD = 0.f;
    float2 vL2 = f2(0, 0), vR2 = f2(0, 0), vS2 = f2(0, 0);
    const float2 inv9_2 = f2(1.f/9.f, 1.f/9.f);
    const float2 C1_2 = f2(1e-4f, 1e-4f);
    const float2 C2_2 = f2(9e-4f, 9e-4f);
    const float2 two2 = f2(2.f, 2.f);
    const float third = 1.f / 3.f;

    // ---- pipeline prologue ----
    float2 dA = loadPair(dmy, ys * W);
    float2 dB = (ys + 1 <= ye) ? loadPair(dmy, (ys + 1) * W) : f2(0, 0);
    Row cur = issue(ys, dA);
    Row nxt;

    for (int y = ys; y <= ye; y++) {
        float2 dC = (y + 2 <= ye) ? loadPair(dmy, (y + 2) * W) : f2(0, 0);
        if (y + 1 <= ye) nxt = issue(y + 1, dB);

        // ---- process row y ----
        float2 d = cur.d;
        float2 oth = fma2(cur.wf, sub2(cur.o1, cur.o0), cur.o0);
        float2 dn = f2(d.y, __shfl_down_sync(FULLMASK, d.x, 1));

        float2 a[3], e[3], an[3], hs[3][5];
        #pragma unroll
        for (int c = 0; c < 3; c++) {
            a[c] = cur.a[c];
            e[c] = fma2(cur.wf, sub2(cur.e1[c], cur.e0[c]), cur.e0[c]);
            float2 aa = mul2(a[c], a[c]);
            float2 ee = mul2(e[c], e[c]);
            float2 ae = mul2(a[c], e[c]);
            float2 q[5] = {a[c], e[c], aa, ee, ae};
            float adn = 0.f;
            #pragma unroll
            for (int k = 0; k < 5; k++) {
                float s = q[k].x + q[k].y;
                float up = __shfl_up_sync(FULLMASK, q[k].y, 1);
                float dw = __shfl_down_sync(FULLMASK, q[k].x, 1);
                if (k == 0) adn = dw;
                hs[c][k] = f2(up + s, s + dw);
            }
            an[c] = f2(a[c].y, adn);
        }

        bool own  = (y >= y0) & (y < y0 + CH);
        bool ownp = (y - 1 >= y0) & (y - 1 < y0 + CH);

        if (own) {
            #pragma unroll
            for (int c = 0; c < 3; c++)
                vL2 = fma2(mL, abs2(sub2(a[c], e[c])), vL2);
            vR2 = fma2(mL, abs2(sub2(d, oth)), vR2);
            // x-smoothness
            float2 gx2 = abs2(sub2(a[0], an[0]));
            gx2 = add2(gx2, abs2(sub2(a[1], an[1])));
            gx2 = add2(gx2, abs2(sub2(a[2], an[2])));
            float2 expv = f2(__expf(-gx2.x * third), __expf(-gx2.y * third));
            vS2 = fma2(mX, abs2(mul2(sub2(d, dn), expv)), vS2);
        }
        if (ownp) {
            // y-smoothness for row y-1
            float2 gy2 = abs2(sub2(pX[0], a[0]));
            gy2 = add2(gy2, abs2(sub2(pX[1], a[1])));
            gy2 = add2(gy2, abs2(sub2(pX[2], a[2])));
            float2 expv = f2(__expf(-gy2.x * third), __expf(-gy2.y * third));
            vS2 = fma2(mL, abs2(mul2(sub2(pd, d), expv)), vS2);
            if ((y - 1 >= 1) & (y - 1 <= H - 2)) {
                #pragma unroll
                for (int c = 0; c < 3; c++) {
                    float2 Sa  = add2(s2[c][0], hs[c][0]);
                    float2 Se  = add2(s2[c][1], hs[c][1]);
                    float2 Saa = add2(s2[c][2], hs[c][2]);
                    float2 See = add2(s2[c][3], hs[c][3]);
                    float2 Sae = add2(s2[c][4], hs[c][4]);
                    float2 mux = mul2(Sa, inv9_2);
                    float2 muy = mul2(Se, inv9_2);
                    float2 mxy = mul2(mux, muy);
                    float2 sigx = sub2(mul2(Saa, inv9_2), mul2(mux, mux));
                    float2 sigy = sub2(mul2(See, inv9_2), mul2(muy, muy));
                    float2 cov  = sub2(mul2(Sae, inv9_2), mxy);
                    float2 num = mul2(fma2(two2, mxy, C1_2), fma2(two2, cov, C2_2));
                    float2 den = mul2(add2(fma2(mux, mux, mul2(muy, muy)), C1_2),
                                      add2(add2(sigx, sigy), C2_2));
                    float sx = __saturatef((1.f - __fdividef(num.x, den.x)) * 0.5f);
                    float sy = __saturatef((1.f - __fdividef(num.y, den.y)) * 0.5f);
                    vD = fmaf(mD.x, sx, vD);
                    vD = fmaf(mD.y, sy, vD);
                }
            }
        }

        // rotate vertical ring + prev-row state
        #pragma unroll
        for (int c = 0; c < 3; c++) {
            #pragma unroll
            for (int k = 0; k < 5; k++) {
                float2 t = hs[c][k];
                s2[c][k] = add2(s1[c][k], t);
                s1[c][k] = t;
            }
            pX[c] = a[c];
        }
        pd = d;

        cur = nxt;
        dB = dC;
    }

    float v[4];
    v[0] = vD;
    v[1] = vL2.x + vL2.y;
    v[2] = vR2.x + vR2.y;
    v[3] = vS2.x + vS2.y;
    block_accumulate2<4>(v, g_acc + lvl * 8 + side);
}

// ---------------- final combine ----------------
__global__ void final_kernel(float* __restrict__ out) {
    double AP = 0.0, LR = 0.0, DS = 0.0;
    for (int i = 0; i < 4; i++) {
        int Hi = H0 >> i, Wi = W0 >> i;
        double Nd = (double)BB * 3.0 * (Hi - 2) * (Wi - 2);
        double Nl = (double)BB * 3.0 * Hi * Wi;
        double Np = (double)BB * Hi * Wi;
        const double* a = g_acc + i * 8;
        AP += 0.85 * (a[0] + a[1]) / Nd + 0.15 * (a[2] + a[3]) / Nl;
        LR += (a[4] + a[5]) / Np;
        DS += (a[6] + a[7]) / Np / (double)(1 << i);
    }
    AP *= 0.85;
    DS *= 0.1;
    double total = AP + LR + DS;
    out[0] = (float)total;
    out[1] = (float)AP;
    out[2] = (float)LR;
    out[3] = (float)DS;
}

// ---------------- host launcher ----------------
extern "C" void kernel_launch(void* const* d_in, const int* in_sizes, int n_in,
                              void* d_out, int out_size) {
    const float* disp0 = (const float*)d_in[0];
    const float* disp1 = (const float*)d_in[1];
    const float* disp2 = (const float*)d_in[2];
    const float* disp3 = (const float*)d_in[3];
    const float* left  = (const float*)d_in[4];
    const float* right = (const float*)d_in[5];
    float* out = (float*)d_out;

    static bool init = false;
    static float *lp1, *rp1, *lp2, *rp2, *lp3, *rp3;
    if (!init) {
        cudaGetSymbolAddress((void**)&lp1, g_lp1);
        cudaGetSymbolAddress((void**)&rp1, g_rp1);
        cudaGetSymbolAddress((void**)&lp2, g_lp2);
        cudaGetSymbolAddress((void**)&rp2, g_rp2);
        cudaGetSymbolAddress((void**)&lp3, g_lp3);
        cudaGetSymbolAddress((void**)&rp3, g_rp3);
        init = true;
    }

    zero_acc_kernel<<<1, 32>>>();

    const int BC = BB * 3;
    {
        int n1 = BC * 128 * 256;
        resize2_kernel<<<(2*n1 + 255) / 256, 256>>>(left, lp1, right, rp1, BC, 256, 512, 128, 256);
        int n2 = BC * 64 * 128;
        resize2_kernel<<<(2*n2 + 255) / 256, 256>>>(lp1, lp2, rp1, rp2, BC, 128, 256, 64, 128);
        int n3 = BC * 32 * 64;
        resize2_kernel<<<(2*n3 + 255) / 256, 256>>>(lp2, lp3, rp2, rp3, BC, 64, 128, 32, 64);
    }

    LevelArgs args;
    args.lp[0] = left;  args.lp[1] = lp1; args.lp[2] = lp2; args.lp[3] = lp3;
    args.rp[0] = right; args.rp[1] = rp1; args.rp[2] = rp2; args.rp[3] = rp3;
    args.disp[0] = disp0; args.disp[1] = disp1; args.disp[2] = disp2; args.disp[3] = disp3;

    fused_all_kernel<<<NBLOCKS, NT>>>(args);

    final_kernel<<<1, 1>>>(out);
}

// round 9
// speedup vs baseline: 1.3116x; 1.3116x over previous
#include <cuda_runtime.h>
#include <math.h>

#define BB 32
#define H0 256
#define W0 512
#define NT 128            // 4 warps per block
#define FULLMASK 0xffffffffu

// per side: L0 2304, L1 576, L2 160, L3 96 = 3136 warps; two sides = 6272
#define L1_BASE 2304
#define L2_BASE 2880
#define L3_BASE 3040
#define SIDE_WARPS 3136
#define TOTAL_WARPS (SIDE_WARPS * 2)
#define NBLOCKS (TOTAL_WARPS / 4)   // 1568

// ---------------- scratch ----------------
__device__ float g_lp1[BB*3*128*256];
__device__ float g_rp1[BB*3*128*256];
__device__ float g_lp2[BB*3*64*128];
__device__ float g_rp2[BB*3*64*128];
__device__ float g_lp3[BB*3*32*64];
__device__ float g_rp3[BB*3*32*64];

// per level i, 8 slots: 0 dssim_l, 1 dssim_r, 2 l1_l, 3 l1_r, 4 lr_l, 5 lr_r, 6 ds_l, 7 ds_r
__device__ double g_acc[32];

// ---------------- reduction helper (stride-2 slots) ----------------
template<int NV>
__device__ __forceinline__ void block_accumulate2(float (&v)[NV], double* accs) {
    #pragma unroll
    for (int k = 0; k < NV; k++)
        #pragma unroll
        for (int o = 16; o > 0; o >>= 1)
            v[k] += __shfl_down_sync(FULLMASK, v[k], o);
    __shared__ float sh[NV][4];
    int lane = threadIdx.x & 31, w = threadIdx.x >> 5;
    if (lane == 0) {
        #pragma unroll
        for (int k = 0; k < NV; k++) sh[k][w] = v[k];
    }
    __syncthreads();
    if (threadIdx.x == 0) {
        #pragma unroll
        for (int k = 0; k < NV; k++) {
            float s = sh[k][0] + sh[k][1] + sh[k][2] + sh[k][3];
            atomicAdd(accs + 2 * k, (double)s);
        }
    }
}

// ---------------- paired bilinear align-corners resize (+acc zeroing) -------
__global__ void resize2_kernel(const float* __restrict__ srcA, float* __restrict__ dstA,
                               const float* __restrict__ srcB, float* __restrict__ dstB,
                               int BC, int h, int w, int nh, int nw, int zero_accs) {
    if (zero_accs && blockIdx.x == 0 && threadIdx.x < 32) g_acc[threadIdx.x] = 0.0;
    int idx = blockIdx.x * blockDim.x + threadIdx.x;
    int total = BC * nh * nw;
    int which = 0;
    if (idx >= total) { idx -= total; which = 1; if (idx >= total) return; }
    const float* src = which ? srcB : srcA;
    float* dst = which ? dstB : dstA;
    int x  = idx % nw;
    int t  = idx / nw;
    int y  = t % nh;
    int bc = t / nh;
    float fy = (float)y * (float)(h - 1) / (float)(nh - 1);
    float fx = (float)x * (float)(w - 1) / (float)(nw - 1);
    int y0 = (int)floorf(fy); int y1 = min(y0 + 1, h - 1);
    int x0 = (int)floorf(fx); int x1 = min(x0 + 1, w - 1);
    float wy = fy - (float)y0, wx = fx - (float)x0;
    const float* s = src + (size_t)bc * h * w;
    float top = s[(size_t)y0 * w + x0] * (1.f - wx) + s[(size_t)y0 * w + x1] * wx;
    float bot = s[(size_t)y1 * w + x0] * (1.f - wx) + s[(size_t)y1 * w + x1] * wx;
    dst[idx] = top * (1.f - wy) + bot * wy;
}

// ---------------- fused loss: side-split + 2-stage pipeline + unroll-2 ------
struct LevelArgs {
    const float* lp[4];
    const float* rp[4];
    const float* disp[4];
};

struct Row {
    float d;
    float o0, o1, wf;
    float a[3];
    float e0[3], e1[3];
};

__global__ __launch_bounds__(NT) void fused_all_kernel(LevelArgs args) {
    int lane = threadIdx.x & 31;
    int g = blockIdx.x * (NT / 32) + (threadIdx.x >> 5);
    int side = (g >= SIDE_WARPS) ? 1 : 0;
    g -= side * SIDE_WARPS;

    int lvl, base, wpi, nx, W, H, CH;
    if (g < L1_BASE)      { lvl = 0; base = 0;       wpi = 72; nx = 18; W = 512; H = 256; CH = 64; }
    else if (g < L2_BASE) { lvl = 1; base = L1_BASE; wpi = 18; nx = 9;  W = 256; H = 128; CH = 64; }
    else if (g < L3_BASE) { lvl = 2; base = L2_BASE; wpi = 5;  nx = 5;  W = 128; H = 64;  CH = 64; }
    else                  { lvl = 3; base = L3_BASE; wpi = 3;  nx = 3;  W = 64;  H = 32;  CH = 32; }

    int r   = g - base;
    int b   = r / wpi;
    int rr  = r - b * wpi;
    int xsl = rr % nx;
    int ych = rr / nx;
    int y0  = ych * CH;
    int x   = xsl * 30 + lane - 1;

    int plane = H * W;
    const float* Ximg = side ? args.rp[lvl] : args.lp[lvl];
    const float* Gimg = side ? args.lp[lvl] : args.rp[lvl];
    const float* dbase = args.disp[lvl] + (size_t)b * 2 * plane;
    const float* dmy  = dbase + (side ? plane : 0);
    const float* doth = dbase + (side ? 0 : plane);
    float sgn = side ? (float)(W - 1) : -(float)(W - 1);

    bool inx = (x >= 0) & (x < W);
    bool lane_emit = (lane >= 1) & (lane <= 30) & (x < W);
    bool dss_x = lane_emit & (x >= 1) & (x <= W - 2);

    int ys = max(y0 - 2, 0);
    int ye = min(y0 + CH, H - 1);

    const float* Xb[3];
    const float* Gb[3];
    #pragma unroll
    for (int c = 0; c < 3; c++) {
        Xb[c] = Ximg + ((size_t)b * 3 + c) * plane;
        Gb[c] = Gimg + ((size_t)b * 3 + c) * plane;
    }

    auto issue = [&](int y, float d) -> Row {
        Row rv;
        rv.d = d;
        float xwf = (float)x + d * sgn;
        float fw = floorf(xwf); int x0i = (int)fw; float wf = xwf - fw;
        bool v0 = (x0i >= 0) & (x0i < W);
        bool v1 = (x0i >= -1) & (x0i < W - 1);
        rv.wf = wf;
        int off = y * W;
        rv.o0 = v0 ? __ldg(doth + off + x0i) : 0.f;
        rv.o1 = v1 ? __ldg(doth + off + x0i + 1) : 0.f;
        #pragma unroll
        for (int c = 0; c < 3; c++) {
            rv.a[c]  = inx ? __ldg(Xb[c] + off + x) : 0.f;
            rv.e0[c] = v0 ? __ldg(Gb[c] + off + x0i) : 0.f;
            rv.e1[c] = v1 ? __ldg(Gb[c] + off + x0i + 1) : 0.f;
        }
        return rv;
    };

    float s2[3][5], s1[3][5];
    #pragma unroll
    for (int c = 0; c < 3; c++)
        #pragma unroll
        for (int k = 0; k < 5; k++) { s2[c][k] = 0.f; s1[c][k] = 0.f; }
    float pX[3] = {0.f, 0.f, 0.f};
    float pd = 0.f;

    float v[4] = {0.f, 0.f, 0.f, 0.f};   // dssim, l1, lr, ds
    const float inv9 = 1.f / 9.f;
    const float C1v = 1e-4f, C2v = 9e-4f, third = 1.f / 3.f;

    auto process = [&](int y, const Row& cur) {
        float d = cur.d;
        float w1 = cur.wf, w0 = 1.f - cur.wf;
        float oth = cur.o0 * w0 + cur.o1 * w1;
        float nd = __shfl_down_sync(FULLMASK, d, 1);

        float Xv[3], Ev[3], nXv[3], hs[3][5];
        #pragma unroll
        for (int c = 0; c < 3; c++) {
            float a = cur.a[c];
            float e = cur.e0[c] * w0 + cur.e1[c] * w1;
            Xv[c] = a; Ev[c] = e;
            nXv[c] = __shfl_down_sync(FULLMASK, a, 1);
            float q0 = a, q1 = e, q2 = a * a, q3 = e * e, q4 = a * e;
            hs[c][0] = __shfl_up_sync(FULLMASK, q0, 1) + q0 + __shfl_down_sync(FULLMASK, q0, 1);
            hs[c][1] = __shfl_up_sync(FULLMASK, q1, 1) + q1 + __shfl_down_sync(FULLMASK, q1, 1);
            hs[c][2] = __shfl_up_sync(FULLMASK, q2, 1) + q2 + __shfl_down_sync(FULLMASK, q2, 1);
            hs[c][3] = __shfl_up_sync(FULLMASK, q3, 1) + q3 + __shfl_down_sync(FULLMASK, q3, 1);
            hs[c][4] = __shfl_up_sync(FULLMASK, q4, 1) + q4 + __shfl_down_sync(FULLMASK, q4, 1);
        }

        bool own  = (y >= y0) & (y < y0 + CH);
        bool ownp = (y - 1 >= y0) & (y - 1 < y0 + CH);

        if (lane_emit) {
            if (own) {
                v[1] += fabsf(Xv[0] - Ev[0]) + fabsf(Xv[1] - Ev[1]) + fabsf(Xv[2] - Ev[2]);
                v[2] += fabsf(d - oth);
                if (x < W - 1) {
                    float gx = fabsf(Xv[0]-nXv[0]) + fabsf(Xv[1]-nXv[1]) + fabsf(Xv[2]-nXv[2]);
                    v[3] += fabsf((d - nd) * __expf(-gx * third));
                }
            }
            if (ownp) {
                float gy = fabsf(pX[0]-Xv[0]) + fabsf(pX[1]-Xv[1]) + fabsf(pX[2]-Xv[2]);
                v[3] += fabsf((pd - d) * __expf(-gy * third));
            }
            if (ownp & (y - 1 >= 1) & (y - 1 <= H - 2) & dss_x) {
                #pragma unroll
                for (int c = 0; c < 3; c++) {
                    float Sa  = s2[c][0] + hs[c][0];
                    float Se  = s2[c][1] + hs[c][1];
                    float Saa = s2[c][2] + hs[c][2];
                    float See = s2[c][3] + hs[c][3];
                    float Sae = s2[c][4] + hs[c][4];
                    float mux = Sa * inv9, muy = Se * inv9;
                    float sigx = Saa * inv9 - mux * mux;
                    float sigy = See * inv9 - muy * muy;
                    float cov  = Sae * inv9 - mux * muy;
                    float ssim = __fdividef((2.f*mux*muy + C1v) * (2.f*cov + C2v),
                                            (mux*mux + muy*muy + C1v) * (sigx + sigy + C2v));
                    v[0] += __saturatef((1.f - ssim) * 0.5f);
                }
            }
        }

        #pragma unroll
        for (int c = 0; c < 3; c++)
            #pragma unroll
            for (int k = 0; k < 5; k++) {
                float t = hs[c][k];
                s2[c][k] = s1[c][k] + t;
                s1[c][k] = t;
            }
        pX[0] = Xv[0]; pX[1] = Xv[1]; pX[2] = Xv[2];
        pd = d;
    };

    // ---- pipeline prologue ----
    float dIn = inx ? __ldg(dmy + ys * W + x) : 0.f;
    float dB = (ys + 1 <= ye && inx) ? __ldg(dmy + (ys + 1) * W + x) : 0.f;
    Row A = issue(ys, dIn);
    Row B;

    int y = ys;
    // unroll-2 main loop: invariant at top: A = row y, dB = disp(y+1)
    for (; y + 1 <= ye; y += 2) {
        float dC = (y + 2 <= ye && inx) ? __ldg(dmy + (y + 2) * W + x) : 0.f;
        B = issue(y + 1, dB);
        process(y, A);

        float dD = (y + 3 <= ye && inx) ? __ldg(dmy + (y + 3) * W + x) : 0.f;
        if (y + 2 <= ye) A = issue(y + 2, dC);
        process(y + 1, B);
        dB = dD;
    }
    if (y <= ye) process(y, A);

    block_accumulate2<4>(v, g_acc + lvl * 8 + side);
}

// ---------------- final combine ----------------
__global__ void final_kernel(float* __restrict__ out) {
    double AP = 0.0, LR = 0.0, DS = 0.0;
    for (int i = 0; i < 4; i++) {
        int Hi = H0 >> i, Wi = W0 >> i;
        double Nd = (double)BB * 3.0 * (Hi - 2) * (Wi - 2);
        double Nl = (double)BB * 3.0 * Hi * Wi;
        double Np = (double)BB * Hi * Wi;
        const double* a = g_acc + i * 8;
        AP += 0.85 * (a[0] + a[1]) / Nd + 0.15 * (a[2] + a[3]) / Nl;
        LR += (a[4] + a[5]) / Np;
        DS += (a[6] + a[7]) / Np / (double)(1 << i);
    }
    AP *= 0.85;
    DS *= 0.1;
    double total = AP + LR + DS;
    out[0] = (float)total;
    out[1] = (float)AP;
    out[2] = (float)LR;
    out[3] = (float)DS;
}

// ---------------- host launcher ----------------
extern "C" void kernel_launch(void* const* d_in, const int* in_sizes, int n_in,
                              void* d_out, int out_size) {
    const float* disp0 = (const float*)d_in[0];
    const float* disp1 = (const float*)d_in[1];
    const float* disp2 = (const float*)d_in[2];
    const float* disp3 = (const float*)d_in[3];
    const float* left  = (const float*)d_in[4];
    const float* right = (const float*)d_in[5];
    float* out = (float*)d_out;

    static bool init = false;
    static float *lp1, *rp1, *lp2, *rp2, *lp3, *rp3;
    if (!init) {
        cudaGetSymbolAddress((void**)&lp1, g_lp1);
        cudaGetSymbolAddress((void**)&rp1, g_rp1);
        cudaGetSymbolAddress((void**)&lp2, g_lp2);
        cudaGetSymbolAddress((void**)&rp2, g_rp2);
        cudaGetSymbolAddress((void**)&lp3, g_lp3);
        cudaGetSymbolAddress((void**)&rp3, g_rp3);
        init = true;
    }

    const int BC = BB * 3;
    {
        int n1 = BC * 128 * 256;
        resize2_kernel<<<(2*n1 + 255) / 256, 256>>>(left, lp1, right, rp1, BC, 256, 512, 128, 256, 1);
        int n2 = BC * 64 * 128;
        resize2_kernel<<<(2*n2 + 255) / 256, 256>>>(lp1, lp2, rp1, rp2, BC, 128, 256, 64, 128, 0);
        int n3 = BC * 32 * 64;
        resize2_kernel<<<(2*n3 + 255) / 256, 256>>>(lp2, lp3, rp2, rp3, BC, 64, 128, 32, 64, 0);
    }

    LevelArgs args;
    args.lp[0] = left;  args.lp[1] = lp1; args.lp[2] = lp2; args.lp[3] = lp3;
    args.rp[0] = right; args.rp[1] = rp1; args.rp[2] = rp2; args.rp[3] = rp3;
    args.disp[0] = disp0; args.disp[1] = disp1; args.disp[2] = disp2; args.disp[3] = disp3;

    fused_all_kernel<<<NBLOCKS, NT>>>(args);

    final_kernel<<<1, 1>>>(out);
}

// round 10
// speedup vs baseline: 1.5361x; 1.1712x over previous
#include <cuda_runtime.h>
#include <math.h>

#define BB 32
#define H0 256
#define W0 512
#define NT 128            // 4 warps per block
#define FULLMASK 0xffffffffu

// per side: L0 2304, L1 576, L2 160, L3 96 = 3136 warps; two sides = 6272
#define L1_BASE 2304
#define L2_BASE 2880
#define L3_BASE 3040
#define SIDE_WARPS 3136
#define TOTAL_WARPS (SIDE_WARPS * 2)
#define NBLOCKS (TOTAL_WARPS / 4)   // 1568

// ---------------- scratch ----------------
__device__ float g_lp1[BB*3*128*256];
__device__ float g_rp1[BB*3*128*256];
__device__ float g_lp2[BB*3*64*128];
__device__ float g_rp2[BB*3*64*128];
__device__ float g_lp3[BB*3*32*64];
__device__ float g_rp3[BB*3*32*64];

// per level i, 8 slots: 0 dssim_l, 1 dssim_r, 2 l1_l, 3 l1_r, 4 lr_l, 5 lr_r, 6 ds_l, 7 ds_r
__device__ double g_acc[32];

// ---------------- reduction helper (stride-2 slots) ----------------
template<int NV>
__device__ __forceinline__ void block_accumulate2(float (&v)[NV], double* accs) {
    #pragma unroll
    for (int k = 0; k < NV; k++)
        #pragma unroll
        for (int o = 16; o > 0; o >>= 1)
            v[k] += __shfl_down_sync(FULLMASK, v[k], o);
    __shared__ float sh[NV][4];
    int lane = threadIdx.x & 31, w = threadIdx.x >> 5;
    if (lane == 0) {
        #pragma unroll
        for (int k = 0; k < NV; k++) sh[k][w] = v[k];
    }
    __syncthreads();
    if (threadIdx.x == 0) {
        #pragma unroll
        for (int k = 0; k < NV; k++) {
            float s = sh[k][0] + sh[k][1] + sh[k][2] + sh[k][3];
            atomicAdd(accs + 2 * k, (double)s);
        }
    }
}

// ---------------- paired bilinear align-corners resize (+acc zeroing) -------
__global__ void resize2_kernel(const float* __restrict__ srcA, float* __restrict__ dstA,
                               const float* __restrict__ srcB, float* __restrict__ dstB,
                               int BC, int h, int w, int nh, int nw, int zero_accs) {
    if (zero_accs && blockIdx.x == 0 && threadIdx.x < 32) g_acc[threadIdx.x] = 0.0;
    int idx = blockIdx.x * blockDim.x + threadIdx.x;
    int total = BC * nh * nw;
    int which = 0;
    if (idx >= total) { idx -= total; which = 1; if (idx >= total) return; }
    const float* src = which ? srcB : srcA;
    float* dst = which ? dstB : dstA;
    int x  = idx % nw;
    int t  = idx / nw;
    int y  = t % nh;
    int bc = t / nh;
    float fy = (float)y * (float)(h - 1) / (float)(nh - 1);
    float fx = (float)x * (float)(w - 1) / (float)(nw - 1);
    int y0 = (int)floorf(fy); int y1 = min(y0 + 1, h - 1);
    int x0 = (int)floorf(fx); int x1 = min(x0 + 1, w - 1);
    float wy = fy - (float)y0, wx = fx - (float)x0;
    const float* s = src + (size_t)bc * h * w;
    float top = s[(size_t)y0 * w + x0] * (1.f - wx) + s[(size_t)y0 * w + x1] * wx;
    float bot = s[(size_t)y1 * w + x0] * (1.f - wx) + s[(size_t)y1 * w + x1] * wx;
    dst[idx] = top * (1.f - wy) + bot * wy;
}

// ---------------- fused loss: side-split + 2-stage pipeline -----------------
struct LevelArgs {
    const float* lp[4];
    const float* rp[4];
    const float* disp[4];
};

struct Row {
    float d;
    float o0, o1, wf;
    float a[3];
    float e0[3], e1[3];
};

__global__ __launch_bounds__(NT) void fused_all_kernel(LevelArgs args) {
    int lane = threadIdx.x & 31;
    int g = blockIdx.x * (NT / 32) + (threadIdx.x >> 5);
    int side = (g >= SIDE_WARPS) ? 1 : 0;
    g -= side * SIDE_WARPS;

    int lvl, base, wpi, nx, W, H, CH;
    if (g < L1_BASE)      { lvl = 0; base = 0;       wpi = 72; nx = 18; W = 512; H = 256; CH = 64; }
    else if (g < L2_BASE) { lvl = 1; base = L1_BASE; wpi = 18; nx = 9;  W = 256; H = 128; CH = 64; }
    else if (g < L3_BASE) { lvl = 2; base = L2_BASE; wpi = 5;  nx = 5;  W = 128; H = 64;  CH = 64; }
    else                  { lvl = 3; base = L3_BASE; wpi = 3;  nx = 3;  W = 64;  H = 32;  CH = 32; }

    int r   = g - base;
    int b   = r / wpi;
    int rr  = r - b * wpi;
    int xsl = rr % nx;
    int ych = rr / nx;
    int y0  = ych * CH;
    int x   = xsl * 30 + lane - 1;

    int plane = H * W;
    const float* Ximg = side ? args.rp[lvl] : args.lp[lvl];
    const float* Gimg = side ? args.lp[lvl] : args.rp[lvl];
    const float* dbase = args.disp[lvl] + (size_t)b * 2 * plane;
    const float* dmy  = dbase + (side ? plane : 0);
    const float* doth = dbase + (side ? 0 : plane);
    float sgn = side ? (float)(W - 1) : -(float)(W - 1);

    bool inx = (x >= 0) & (x < W);
    bool lane_emit = (lane >= 1) & (lane <= 30) & (x < W);
    bool dss_x = lane_emit & (x >= 1) & (x <= W - 2);

    int ys = max(y0 - 2, 0);
    int ye = min(y0 + CH, H - 1);

    const float* Xb[3];
    const float* Gb[3];
    #pragma unroll
    for (int c = 0; c < 3; c++) {
        Xb[c] = Ximg + ((size_t)b * 3 + c) * plane;
        Gb[c] = Gimg + ((size_t)b * 3 + c) * plane;
    }

    auto issue = [&](int y, float d) -> Row {
        Row rv;
        rv.d = d;
        float xwf = (float)x + d * sgn;
        float fw = floorf(xwf); int x0i = (int)fw; float wf = xwf - fw;
        bool v0 = (x0i >= 0) & (x0i < W);
        bool v1 = (x0i >= -1) & (x0i < W - 1);
        rv.wf = wf;
        int off = y * W;
        rv.o0 = v0 ? __ldg(doth + off + x0i) : 0.f;
        rv.o1 = v1 ? __ldg(doth + off + x0i + 1) : 0.f;
        #pragma unroll
        for (int c = 0; c < 3; c++) {
            rv.a[c]  = inx ? __ldg(Xb[c] + off + x) : 0.f;
            rv.e0[c] = v0 ? __ldg(Gb[c] + off + x0i) : 0.f;
            rv.e1[c] = v1 ? __ldg(Gb[c] + off + x0i + 1) : 0.f;
        }
        return rv;
    };

    float s2[3][5], s1[3][5];
    #pragma unroll
    for (int c = 0; c < 3; c++)
        #pragma unroll
        for (int k = 0; k < 5; k++) { s2[c][k] = 0.f; s1[c][k] = 0.f; }
    float pX[3] = {0.f, 0.f, 0.f};
    float pd = 0.f;

    float v[4] = {0.f, 0.f, 0.f, 0.f};   // dssim, l1, lr, ds
    const float inv9 = 1.f / 9.f;
    const float C1v = 1e-4f, C2v = 9e-4f, third = 1.f / 3.f;

    auto process = [&](int y, const Row& cur) {
        float d = cur.d;
        float w1 = cur.wf, w0 = 1.f - cur.wf;
        float oth = cur.o0 * w0 + cur.o1 * w1;
        float nd = __shfl_down_sync(FULLMASK, d, 1);

        float Xv[3], Ev[3], nXv[3], hs[3][5];
        #pragma unroll
        for (int c = 0; c < 3; c++) {
            float a = cur.a[c];
            float e = cur.e0[c] * w0 + cur.e1[c] * w1;
            Xv[c] = a; Ev[c] = e;
            // shuffle only raw values; rebuild neighbor products locally
            float am = __shfl_up_sync(FULLMASK, a, 1);
            float ap = __shfl_down_sync(FULLMASK, a, 1);
            float em = __shfl_up_sync(FULLMASK, e, 1);
            float ep = __shfl_down_sync(FULLMASK, e, 1);
            nXv[c] = ap;
            hs[c][0] = (am + a) + ap;
            hs[c][1] = (em + e) + ep;
            hs[c][2] = (am * am + a * a) + ap * ap;
            hs[c][3] = (em * em + e * e) + ep * ep;
            hs[c][4] = (am * em + a * e) + ap * ep;
        }

        bool own  = (y >= y0) & (y < y0 + CH);
        bool ownp = (y - 1 >= y0) & (y - 1 < y0 + CH);

        if (lane_emit) {
            if (own) {
                v[1] += fabsf(Xv[0] - Ev[0]) + fabsf(Xv[1] - Ev[1]) + fabsf(Xv[2] - Ev[2]);
                v[2] += fabsf(d - oth);
                if (x < W - 1) {
                    float gx = fabsf(Xv[0]-nXv[0]) + fabsf(Xv[1]-nXv[1]) + fabsf(Xv[2]-nXv[2]);
                    v[3] += fabsf((d - nd) * __expf(-gx * third));
                }
            }
            if (ownp) {
                float gy = fabsf(pX[0]-Xv[0]) + fabsf(pX[1]-Xv[1]) + fabsf(pX[2]-Xv[2]);
                v[3] += fabsf((pd - d) * __expf(-gy * third));
            }
            if (ownp & (y - 1 >= 1) & (y - 1 <= H - 2) & dss_x) {
                #pragma unroll
                for (int c = 0; c < 3; c++) {
                    float Sa  = s2[c][0] + hs[c][0];
                    float Se  = s2[c][1] + hs[c][1];
                    float Saa = s2[c][2] + hs[c][2];
                    float See = s2[c][3] + hs[c][3];
                    float Sae = s2[c][4] + hs[c][4];
                    float mux = Sa * inv9, muy = Se * inv9;
                    float sigx = Saa * inv9 - mux * mux;
                    float sigy = See * inv9 - muy * muy;
                    float cov  = Sae * inv9 - mux * muy;
                    float ssim = __fdividef((2.f*mux*muy + C1v) * (2.f*cov + C2v),
                                            (mux*mux + muy*muy + C1v) * (sigx + sigy + C2v));
                    v[0] += __saturatef((1.f - ssim) * 0.5f);
                }
            }
        }

        #pragma unroll
        for (int c = 0; c < 3; c++)
            #pragma unroll
            for (int k = 0; k < 5; k++) {
                float t = hs[c][k];
                s2[c][k] = s1[c][k] + t;
                s1[c][k] = t;
            }
        pX[0] = Xv[0]; pX[1] = Xv[1]; pX[2] = Xv[2];
        pd = d;
    };

    // ---- pipeline prologue ----
    float dB = (ys + 1 <= ye) ? (inx ? __ldg(dmy + (ys + 1) * W + x) : 0.f) : 0.f;
    Row cur = issue(ys, inx ? __ldg(dmy + ys * W + x) : 0.f);
    Row nxt;

    for (int y = ys; y <= ye; y++) {
        float dC = (y + 2 <= ye) ? (inx ? __ldg(dmy + (y + 2) * W + x) : 0.f) : 0.f;
        if (y + 1 <= ye) nxt = issue(y + 1, dB);

        process(y, cur);

        cur = nxt;
        dB = dC;
    }

    block_accumulate2<4>(v, g_acc + lvl * 8 + side);
}

// ---------------- final combine ----------------
__global__ void final_kernel(float* __restrict__ out) {
    double AP = 0.0, LR = 0.0, DS = 0.0;
    for (int i = 0; i < 4; i++) {
        int Hi = H0 >> i, Wi = W0 >> i;
        double Nd = (double)BB * 3.0 * (Hi - 2) * (Wi - 2);
        double Nl = (double)BB * 3.0 * Hi * Wi;
        double Np = (double)BB * Hi * Wi;
        const double* a = g_acc + i * 8;
        AP += 0.85 * (a[0] + a[1]) / Nd + 0.15 * (a[2] + a[3]) / Nl;
        LR += (a[4] + a[5]) / Np;
        DS += (a[6] + a[7]) / Np / (double)(1 << i);
    }
    AP *= 0.85;
    DS *= 0.1;
    double total = AP + LR + DS;
    out[0] = (float)total;
    out[1] = (float)AP;
    out[2] = (float)LR;
    out[3] = (float)DS;
}

// ---------------- host launcher ----------------
extern "C" void kernel_launch(void* const* d_in, const int* in_sizes, int n_in,
                              void* d_out, int out_size) {
    const float* disp0 = (const float*)d_in[0];
    const float* disp1 = (const float*)d_in[1];
    const float* disp2 = (const float*)d_in[2];
    const float* disp3 = (const float*)d_in[3];
    const float* left  = (const float*)d_in[4];
    const float* right = (const float*)d_in[5];
    float* out = (float*)d_out;

    static bool init = false;
    static float *lp1, *rp1, *lp2, *rp2, *lp3, *rp3;
    if (!init) {
        cudaGetSymbolAddress((void**)&lp1, g_lp1);
        cudaGetSymbolAddress((void**)&rp1, g_rp1);
        cudaGetSymbolAddress((void**)&lp2, g_lp2);
        cudaGetSymbolAddress((void**)&rp2, g_rp2);
        cudaGetSymbolAddress((void**)&lp3, g_lp3);
        cudaGetSymbolAddress((void**)&rp3, g_rp3);
        init = true;
    }

    const int BC = BB * 3;
    {
        int n1 = BC * 128 * 256;
        resize2_kernel<<<(2*n1 + 255) / 256, 256>>>(left, lp1, right, rp1, BC, 256, 512, 128, 256, 1);
        int n2 = BC * 64 * 128;
        resize2_kernel<<<(2*n2 + 255) / 256, 256>>>(lp1, lp2, rp1, rp2, BC, 128, 256, 64, 128, 0);
        int n3 = BC * 32 * 64;
        resize2_kernel<<<(2*n3 + 255) / 256, 256>>>(lp2, lp3, rp2, rp3, BC, 64, 128, 32, 64, 0);
    }

    LevelArgs args;
    args.lp[0] = left;  args.lp[1] = lp1; args.lp[2] = lp2; args.lp[3] = lp3;
    args.rp[0] = right; args.rp[1] = rp1; args.rp[2] = rp2; args.rp[3] = rp3;
    args.disp[0] = disp0; args.disp[1] = disp1; args.disp[2] = disp2; args.disp[3] = disp3;

    fused_all_kernel<<<NBLOCKS, NT>>>(args);

    final_kernel<<<1, 1>>>(out);
}